// round 3
// baseline (speedup 1.0000x reference)
#include <cuda_runtime.h>
#include <cstdint>
#include <math.h>

#define NUM_ROIS 333
#define BATCH    512
#define N_REG    300
#define N_CLS    180
#define EPSV     1e-5f
#define SLOPEV   0.3f
#define SPLITK   16

// -------- static device scratch (no allocations allowed) --------
__device__ int   g_base[NUM_ROIS];
__device__ int   g_size[NUM_ROIS];
__device__ int   g_red [NUM_ROIS];
__device__ int   g_off [NUM_ROIS];
__device__ float g_partial[SPLITK * BATCH * N_REG];

// -------- packed f32x2 helpers (FFMA2 path, 2x fp32 rate) --------
typedef unsigned long long u64;

__device__ __forceinline__ u64 pack2(float lo, float hi) {
    u64 r;
    asm("mov.b64 %0, {%1, %2};" : "=l"(r) : "f"(lo), "f"(hi));
    return r;
}
__device__ __forceinline__ u64 fma2(u64 a, u64 b, u64 c) {
    u64 d;
    asm("fma.rn.f32x2 %0, %1, %2, %3;" : "=l"(d) : "l"(a), "l"(b), "l"(c));
    return d;
}
__device__ __forceinline__ float2 unpack2(u64 v) {
    float lo, hi;
    asm("mov.b64 {%0, %1}, %2;" : "=f"(lo), "=f"(hi) : "l"(v));
    float2 f; f.x = lo; f.y = hi;
    return f;
}

// group-padded smem row index: insert 1 pad float per 8 rows
__device__ __forceinline__ int gp(int row) { return row + (row >> 3); }

// ============================================================
// Setup: derive per-ROI size/base (from idx) and red/off (from src_index)
// ============================================================
__global__ void setup_kernel(const int* __restrict__ idx,
                             const int* __restrict__ src_index,
                             int max_in, int max_out, int total, int C) {
    int t = threadIdx.x;
    for (int r = t; r < NUM_ROIS; r += blockDim.x) {
        const int* row = idx + (size_t)r * max_in;
        int lo = 0, hi = max_in;
        while (lo < hi) {                    // first k with row[k] == total
            int mid = (lo + hi) >> 1;
            if (row[mid] == total) hi = mid; else lo = mid + 1;
        }
        g_size[r] = lo;
        g_base[r] = row[0];
    }
    __shared__ int cnt[NUM_ROIS];
    for (int r = t; r < NUM_ROIS; r += blockDim.x) cnt[r] = 0;
    __syncthreads();
    for (int p = t; p < C; p += blockDim.x)
        atomicAdd(&cnt[src_index[p] / max_out], 1);
    __syncthreads();
    if (t == 0) {
        int off = 0;
        for (int r = 0; r < NUM_ROIS; r++) {
            g_red[r] = cnt[r];
            g_off[r] = off;
            off += cnt[r];
        }
    }
}

// ============================================================
// Stage A: per-ROI GEMM (256 batch x 64 out tile) + BN + leaky -> concat_out
//   z[b,o] = sum_k x[b, base+k] * W_enc[r,o,k] + b_enc[r,o]
// ============================================================
#define A_XS_STRIDE 290   // >= 256 + 256/8 = 288, and 290 % 32 == 2 (conflict-free)
#define A_WS_STRIDE 98    // >=  64 +  64/8 =  72, and  98 % 32 == 2

__global__ __launch_bounds__(256)
void roi_enc_kernel(const float* __restrict__ x,
                    const float* __restrict__ W_enc,
                    const float* __restrict__ b_enc,
                    const float* __restrict__ gamma,
                    const float* __restrict__ beta,
                    const float* __restrict__ rmean,
                    const float* __restrict__ rvar,
                    float* __restrict__ concat_out,
                    int total, int max_in, int max_out, int C) {
    const int r    = blockIdx.x;
    const int b0   = blockIdx.y * 256;
    const int ot   = blockIdx.z * 64;
    const int size = g_size[r];
    const int red  = g_red[r];
    const int base = g_base[r];
    const int ooff = g_off[r];
    if (ot >= red) return;   // uniform per block

    __shared__ float Xs[16 * A_XS_STRIDE];
    __shared__ float Ws[16 * A_WS_STRIDE];

    const int tid = threadIdx.x;
    const int tb  = tid >> 3;   // 0..31 : batch group of 8
    const int to  = tid & 7;    // 0..7  : out   group of 8
    const int xro = tb * 9;     // gp(tb*8)
    const int wro = to * 9;     // gp(to*8)

    u64 acc[8][4];
    #pragma unroll
    for (int i = 0; i < 8; i++)
        #pragma unroll
        for (int j = 0; j < 4; j++) acc[i][j] = 0ull;

    for (int k0 = 0; k0 < size; k0 += 16) {
        // --- load X tile: 256 rows x 16 cols, coalesced along k ---
        #pragma unroll
        for (int it = 0; it < 16; it++) {
            int v   = tid + it * 256;
            int row = v >> 4;
            int col = v & 15;
            int k   = k0 + col;
            float val = 0.f;
            if (k < size) val = x[(size_t)(b0 + row) * total + base + k];
            Xs[col * A_XS_STRIDE + gp(row)] = val;
        }
        // --- load W tile: 64 rows (o) x 16 cols ---
        #pragma unroll
        for (int it = 0; it < 4; it++) {
            int v   = tid + it * 256;
            int row = v >> 4;
            int col = v & 15;
            int o   = ot + row;
            int k   = k0 + col;
            float val = 0.f;
            if (o < max_out && k < size)
                val = W_enc[((size_t)r * max_out + o) * max_in + k];
            Ws[col * A_WS_STRIDE + gp(row)] = val;
        }
        __syncthreads();

        #pragma unroll
        for (int kk = 0; kk < 16; kk++) {
            const float* xp = &Xs[kk * A_XS_STRIDE + xro];
            const float* wp = &Ws[kk * A_WS_STRIDE + wro];
            u64 xd[8];
            #pragma unroll
            for (int i = 0; i < 8; i++) { float t = xp[i]; xd[i] = pack2(t, t); }
            u64 wpk[4];
            #pragma unroll
            for (int j = 0; j < 4; j++) wpk[j] = pack2(wp[2 * j], wp[2 * j + 1]);
            #pragma unroll
            for (int i = 0; i < 8; i++)
                #pragma unroll
                for (int j = 0; j < 4; j++)
                    acc[i][j] = fma2(xd[i], wpk[j], acc[i][j]);
        }
        __syncthreads();
    }

    // --- epilogue: bias + BN + leaky, write concat columns ---
    #pragma unroll
    for (int jp = 0; jp < 4; jp++) {
        float2 v2[8];
        #pragma unroll
        for (int i = 0; i < 8; i++) v2[i] = unpack2(acc[i][jp]);
        #pragma unroll
        for (int h = 0; h < 2; h++) {
            int o = ot + to * 8 + jp * 2 + h;
            if (o >= red) continue;
            size_t po = (size_t)r * max_out + o;
            float be  = b_enc[po];
            float ga  = gamma[po];
            float bt  = beta[po];
            float mn  = rmean[po];
            float inv = rsqrtf(rvar[po] + EPSV);
            #pragma unroll
            for (int i = 0; i < 8; i++) {
                int b  = b0 + tb * 8 + i;
                float z = (h ? v2[i].y : v2[i].x) + be;
                float y = ga * (z - mn) * inv + bt;
                y = (y > 0.f) ? y : SLOPEV * y;
                concat_out[(size_t)b * C + ooff + o] = y;
            }
        }
    }
}

// ============================================================
// Stage B: reg_out = concat_out @ W_reg^T  (split-K into g_partial)
// 128x128 tile, 256 threads, 8x8 per thread
// ============================================================
#define B_S_STRIDE 162   // >= 128 + 16 = 144, and 162 % 32 == 2

__global__ __launch_bounds__(256)
void reg_gemm_kernel(const float* __restrict__ concat_out,
                     const float* __restrict__ W_reg, int C) {
    const int m0 = blockIdx.x * 128;
    const int n0 = blockIdx.y * 128;
    const int s  = blockIdx.z;
    const int chunk = (C + SPLITK - 1) / SPLITK;
    const int kbeg  = s * chunk;
    const int kend  = min(C, kbeg + chunk);

    __shared__ float As[16 * B_S_STRIDE];
    __shared__ float Bs[16 * B_S_STRIDE];

    const int tid = threadIdx.x;
    const int tb  = tid >> 4;   // 0..15 : m group of 8
    const int to  = tid & 15;   // 0..15 : n group of 8
    const int aro = tb * 9;
    const int bro = to * 9;

    u64 acc[8][4];
    #pragma unroll
    for (int i = 0; i < 8; i++)
        #pragma unroll
        for (int j = 0; j < 4; j++) acc[i][j] = 0ull;

    for (int k0 = kbeg; k0 < kend; k0 += 16) {
        #pragma unroll
        for (int it = 0; it < 8; it++) {
            int v   = tid + it * 256;
            int row = v >> 4;
            int col = v & 15;
            int k   = k0 + col;
            As[col * B_S_STRIDE + gp(row)] =
                (k < kend) ? concat_out[(size_t)(m0 + row) * C + k] : 0.f;
        }
        #pragma unroll
        for (int it = 0; it < 8; it++) {
            int v   = tid + it * 256;
            int row = v >> 4;
            int col = v & 15;
            int k   = k0 + col;
            int n   = n0 + row;
            Bs[col * B_S_STRIDE + gp(row)] =
                (n < N_REG && k < kend) ? W_reg[(size_t)n * C + k] : 0.f;
        }
        __syncthreads();

        #pragma unroll
        for (int kk = 0; kk < 16; kk++) {
            const float* ap = &As[kk * B_S_STRIDE + aro];
            const float* bp = &Bs[kk * B_S_STRIDE + bro];
            u64 ad[8];
            #pragma unroll
            for (int i = 0; i < 8; i++) { float t = ap[i]; ad[i] = pack2(t, t); }
            u64 bpk[4];
            #pragma unroll
            for (int j = 0; j < 4; j++) bpk[j] = pack2(bp[2 * j], bp[2 * j + 1]);
            #pragma unroll
            for (int i = 0; i < 8; i++)
                #pragma unroll
                for (int j = 0; j < 4; j++)
                    acc[i][j] = fma2(ad[i], bpk[j], acc[i][j]);
        }
        __syncthreads();
    }

    #pragma unroll
    for (int i = 0; i < 8; i++) {
        int m = m0 + tb * 8 + i;
        #pragma unroll
        for (int jp = 0; jp < 4; jp++) {
            float2 v = unpack2(acc[i][jp]);
            int n1 = n0 + to * 8 + jp * 2;
            if (n1 < N_REG)
                g_partial[((size_t)s * BATCH + m) * N_REG + n1] = v.x;
            if (n1 + 1 < N_REG)
                g_partial[((size_t)s * BATCH + m) * N_REG + n1 + 1] = v.y;
        }
    }
}

// ============================================================
// Reduce split-K partials + bias -> reg_out (deterministic)
// ============================================================
__global__ void reg_reduce_kernel(const float* __restrict__ b_reg,
                                  float* __restrict__ reg_out) {
    int i = blockIdx.x * blockDim.x + threadIdx.x;
    if (i >= BATCH * N_REG) return;
    int n = i % N_REG;
    float sum = b_reg[n];
    #pragma unroll
    for (int k = 0; k < SPLITK; k++)
        sum += g_partial[(size_t)k * BATCH * N_REG + i];
    reg_out[i] = sum;
}

// ============================================================
// Stage C: cls GEMV + softmax per batch row
// ============================================================
__global__ __launch_bounds__(256)
void cls_softmax_kernel(const float* __restrict__ reg_out,
                        const float* __restrict__ W_cls,
                        const float* __restrict__ b_cls,
                        float* __restrict__ y_pred) {
    const int m = blockIdx.x;
    const int t = threadIdx.x;
    __shared__ float row[N_REG];
    __shared__ float redbuf[256];

    for (int k = t; k < N_REG; k += 256) row[k] = reg_out[(size_t)m * N_REG + k];
    __syncthreads();

    float logit = -1e30f;
    if (t < N_CLS) {
        float s = b_cls[t];
        const float* w = W_cls + (size_t)t * N_REG;
        #pragma unroll 4
        for (int k = 0; k < N_REG; k++) s = fmaf(w[k], row[k], s);
        logit = s;
    }
    // max reduce
    redbuf[t] = logit;
    __syncthreads();
    #pragma unroll
    for (int off = 128; off > 0; off >>= 1) {
        if (t < off) redbuf[t] = fmaxf(redbuf[t], redbuf[t + off]);
        __syncthreads();
    }
    float mx = redbuf[0];
    __syncthreads();
    float e = (t < N_CLS) ? expf(logit - mx) : 0.f;
    redbuf[t] = e;
    __syncthreads();
    #pragma unroll
    for (int off = 128; off > 0; off >>= 1) {
        if (t < off) redbuf[t] += redbuf[t + off];
        __syncthreads();
    }
    float denom = redbuf[0];
    if (t < N_CLS) y_pred[(size_t)m * N_CLS + t] = e / denom;
}

// ============================================================
// Launch
// ============================================================
extern "C" void kernel_launch(void* const* d_in, const int* in_sizes, int n_in,
                              void* d_out, int out_size) {
    const float* x     = (const float*)d_in[0];
    const float* W_enc = (const float*)d_in[1];
    const float* b_enc = (const float*)d_in[2];
    const float* gamma = (const float*)d_in[3];
    const float* beta  = (const float*)d_in[4];
    const float* rmean = (const float*)d_in[5];
    const float* rvar  = (const float*)d_in[6];
    const float* W_reg = (const float*)d_in[7];
    const float* b_reg = (const float*)d_in[8];
    const float* W_cls = (const float*)d_in[9];
    const float* b_cls = (const float*)d_in[10];
    const int*   idx   = (const int*)d_in[11];
    const int*   srci  = (const int*)d_in[12];

    const int total   = in_sizes[0] / BATCH;
    const int max_out = in_sizes[2] / NUM_ROIS;
    const int max_in  = in_sizes[11] / NUM_ROIS;
    const int C       = in_sizes[12];

    float* out        = (float*)d_out;
    float* concat_out = out;
    float* reg_out    = out + (size_t)BATCH * C;
    float* y_pred     = reg_out + (size_t)BATCH * N_REG;

    setup_kernel<<<1, 512>>>(idx, srci, max_in, max_out, total, C);

    dim3 gA(NUM_ROIS, BATCH / 256, (max_out + 63) / 64);
    roi_enc_kernel<<<gA, 256>>>(x, W_enc, b_enc, gamma, beta, rmean, rvar,
                                concat_out, total, max_in, max_out, C);

    dim3 gB(BATCH / 128, (N_REG + 127) / 128, SPLITK);
    reg_gemm_kernel<<<gB, 256>>>(concat_out, W_reg, C);

    reg_reduce_kernel<<<(BATCH * N_REG + 255) / 256, 256>>>(b_reg, reg_out);

    cls_softmax_kernel<<<BATCH, 256>>>(reg_out, W_cls, b_cls, y_pred);
}

// round 4
// speedup vs baseline: 1.2789x; 1.2789x over previous
#include <cuda_runtime.h>
#include <cstdint>
#include <math.h>

#define NUM_ROIS 333
#define BATCH    512
#define N_REG    300
#define N_CLS    180
#define EPSV     1e-5f
#define SLOPEV   0.3f
#define SPLITK   24

// -------- static device scratch (no allocations allowed) --------
__device__ int   g_base[NUM_ROIS];
__device__ int   g_size[NUM_ROIS];
__device__ int   g_red [NUM_ROIS];
__device__ int   g_off [NUM_ROIS];
__device__ float g_partial[SPLITK * BATCH * N_REG];

typedef unsigned long long u64;

__device__ __forceinline__ u64 fma2(u64 a, u64 b, u64 c) {
    u64 d;
    asm("fma.rn.f32x2 %0, %1, %2, %3;" : "=l"(d) : "l"(a), "l"(b), "l"(c));
    return d;
}
__device__ __forceinline__ float2 unpack2(u64 v) {
    float lo, hi;
    asm("mov.b64 {%0, %1}, %2;" : "=f"(lo), "=f"(hi) : "l"(v));
    return make_float2(lo, hi);
}
__device__ __forceinline__ unsigned sptr(const void* p) {
    return (unsigned)__cvta_generic_to_shared(p);
}
__device__ __forceinline__ void cpa4(unsigned dst, const void* src) {
    asm volatile("cp.async.ca.shared.global [%0], [%1], 4;" :: "r"(dst), "l"(src));
}
__device__ __forceinline__ void cp_commit() { asm volatile("cp.async.commit_group;"); }
__device__ __forceinline__ void cp_wait1()  { asm volatile("cp.async.wait_group 1;" ::: "memory"); }

// ============================================================
// Setup: derive per-ROI size/base (from idx) and red/off (from src_index)
// ============================================================
__global__ void setup_kernel(const int* __restrict__ idx,
                             const int* __restrict__ src_index,
                             int max_in, int max_out, int total, int C) {
    int t = threadIdx.x;
    for (int r = t; r < NUM_ROIS; r += blockDim.x) {
        const int* row = idx + (size_t)r * max_in;
        int lo = 0, hi = max_in;
        while (lo < hi) {                    // first k with row[k] == total
            int mid = (lo + hi) >> 1;
            if (row[mid] == total) hi = mid; else lo = mid + 1;
        }
        g_size[r] = lo;
        g_base[r] = row[0];
    }
    __shared__ int cnt[NUM_ROIS];
    for (int r = t; r < NUM_ROIS; r += blockDim.x) cnt[r] = 0;
    __syncthreads();
    for (int p = t; p < C; p += blockDim.x)
        atomicAdd(&cnt[src_index[p] / max_out], 1);
    __syncthreads();
    if (t == 0) {
        int off = 0;
        for (int r = 0; r < NUM_ROIS; r++) {
            g_red[r] = cnt[r];
            g_off[r] = off;
            off += cnt[r];
        }
    }
}

// ============================================================
// Stage A: per-ROI GEMM (256 batch x 64 out) + BN + leaky -> concat_out
// batch-packed f32x2, W duplicated in smem, cp.async double-buffered
// ============================================================
#define A_XSTR 260                       // floats per k-row of X (256 data + 4 pad)
#define A_WSTR 164                       // floats per k-row of Wdup (8 grp * 20 + 4 pad)
#define A_XSZ  (16 * A_XSTR)             // 4160
#define A_WSZ  (16 * A_WSTR)             // 2624
#define A_SMEM ((2 * A_XSZ + 2 * A_WSZ) * 4)   // 54272 bytes

__global__ __launch_bounds__(256, 2)
void roi_enc_kernel(const float* __restrict__ x, const float* __restrict__ W_enc,
                    const float* __restrict__ b_enc, const float* __restrict__ gamma,
                    const float* __restrict__ beta, const float* __restrict__ rmean,
                    const float* __restrict__ rvar, float* __restrict__ concat_out,
                    int total, int max_in, int max_out, int C)
{
    extern __shared__ float sm[];
    float* Xs = sm;                       // [2][A_XSZ]  Xs[st][k][b]
    float* Ws = sm + 2 * A_XSZ;           // [2][A_WSZ]  dup pairs per o

    const int r    = blockIdx.x;
    const int b0   = blockIdx.y * 256;
    const int size = g_size[r];
    const int red  = g_red[r];
    const int base = g_base[r];
    const int ooff = g_off[r];

    const int tid = threadIdx.x;
    const int tb  = tid >> 3;             // 0..31 batch group (8 b each)
    const int to  = tid & 7;              // 0..7  out group   (8 o each)
    const int fk  = tid & 15;             // fill: fixed k within tile
    const int fr0 = tid >> 4;             // fill: base row

    const float* xg = x + (size_t)b0 * total + base;
    const float* wg = W_enc + (size_t)r * max_out * max_in;
    const unsigned xs_u = sptr(Xs);

    const int nt = (size + 15) >> 4;

    u64 acc[4][8];
    #pragma unroll
    for (int i = 0; i < 4; i++)
        #pragma unroll
        for (int j = 0; j < 8; j++) acc[i][j] = 0ull;

    float wr[4];

    auto fillX = [&](int t, int st) {
        int kg = t * 16 + fk;
        if (kg < size) {
            const float* src = xg + kg;
            unsigned dst = xs_u + (unsigned)(st * A_XSZ + fk * A_XSTR) * 4u;
            #pragma unroll
            for (int it = 0; it < 16; it++) {
                int b = fr0 + it * 16;
                cpa4(dst + (unsigned)b * 4u, src + (size_t)b * total);
            }
        } else {
            float* d = Xs + st * A_XSZ + fk * A_XSTR;
            #pragma unroll
            for (int it = 0; it < 16; it++) d[fr0 + it * 16] = 0.f;
        }
    };
    auto ldgW = [&](int t) {
        int kg = t * 16 + fk;
        #pragma unroll
        for (int it = 0; it < 4; it++) {
            int o = fr0 + it * 16;
            wr[it] = (o < max_out && kg < size) ? wg[(size_t)o * max_in + kg] : 0.f;
        }
    };
    auto stsW = [&](int st) {
        float* d = Ws + st * A_WSZ + fk * A_WSTR;
        #pragma unroll
        for (int it = 0; it < 4; it++) {
            int o = fr0 + it * 16;
            *(float2*)(d + (o >> 3) * 20 + (o & 7) * 2) = make_float2(wr[it], wr[it]);
        }
    };
    auto compute = [&](int st) {
        const float* xb = Xs + st * A_XSZ + tb * 8;
        const float* wb = Ws + st * A_WSZ + to * 20;
        #pragma unroll
        for (int kk = 0; kk < 16; kk++) {
            const ulonglong2* xp = (const ulonglong2*)(xb + kk * A_XSTR);
            const ulonglong2* wp = (const ulonglong2*)(wb + kk * A_WSTR);
            ulonglong2 x01 = xp[0], x23 = xp[1];
            ulonglong2 w01 = wp[0], w23 = wp[1], w45 = wp[2], w67 = wp[3];
            u64 xv[4] = {x01.x, x01.y, x23.x, x23.y};
            u64 wv[8] = {w01.x, w01.y, w23.x, w23.y, w45.x, w45.y, w67.x, w67.y};
            #pragma unroll
            for (int i = 0; i < 4; i++)
                #pragma unroll
                for (int j = 0; j < 8; j++)
                    acc[i][j] = fma2(xv[i], wv[j], acc[i][j]);
        }
    };

    // ---- pipelined mainloop (2-stage) ----
    fillX(0, 0); cp_commit();
    ldgW(0);
    if (nt > 1) fillX(1, 1);
    cp_commit();
    stsW(0);
    if (nt > 1) ldgW(1);
    cp_wait1();
    __syncthreads();

    for (int t = 0; t < nt; t++) {
        int st = t & 1;
        compute(st);
        __syncthreads();
        if (t + 2 < nt) fillX(t + 2, st);
        cp_commit();
        if (t + 1 < nt) stsW(st ^ 1);
        if (t + 2 < nt) ldgW(t + 2);
        cp_wait1();
        __syncthreads();
    }

    // ---- epilogue: BN + leaky, smem transpose, coalesced store ----
    float* Ysm = sm;   // reuse: need 128*65 = 8320 floats (== 2*A_XSZ)
    for (int half = 0; half < 2; half++) {
        __syncthreads();
        if ((tb >> 4) == half) {
            int bl = (tb & 15) * 8;
            #pragma unroll
            for (int j = 0; j < 8; j++) {
                int o = to * 8 + j;
                if (o < red) {
                    size_t po = (size_t)r * max_out + o;
                    float be  = b_enc[po];
                    float ga  = gamma[po];
                    float bt  = beta[po];
                    float mn  = rmean[po];
                    float inv = rsqrtf(rvar[po] + EPSV);
                    #pragma unroll
                    for (int i = 0; i < 4; i++) {
                        float2 v = unpack2(acc[i][j]);
                        float y0 = ga * (v.x + be - mn) * inv + bt;
                        float y1 = ga * (v.y + be - mn) * inv + bt;
                        y0 = (y0 > 0.f) ? y0 : SLOPEV * y0;
                        y1 = (y1 > 0.f) ? y1 : SLOPEV * y1;
                        Ysm[(bl + 2 * i)     * 65 + o] = y0;
                        Ysm[(bl + 2 * i + 1) * 65 + o] = y1;
                    }
                }
            }
        }
        __syncthreads();
        for (int p = tid; p < 128 * 64; p += 256) {
            int bl = p >> 6, o = p & 63;
            if (o < red)
                concat_out[(size_t)(b0 + half * 128 + bl) * C + ooff + o] =
                    Ysm[bl * 65 + o];
        }
    }
}

// ============================================================
// Stage B: reg_out partials = concat_out @ W_reg^T  (split-K)
// 128x128 tile, same FFMA2 structure
// ============================================================
#define B_ASTR 132                       // 128 + 4 pad
#define B_WSTR 324                       // 16 grp * 20 + 4 pad
#define B_ASZ  (16 * B_ASTR)             // 2112
#define B_WSZ  (16 * B_WSTR)             // 5184
#define B_SMEM ((2 * B_ASZ + 2 * B_WSZ) * 4)   // 58368 bytes

__global__ __launch_bounds__(256, 2)
void reg_gemm_kernel(const float* __restrict__ A, const float* __restrict__ Wr, int C)
{
    extern __shared__ float sm[];
    float* As = sm;
    float* Bs = sm + 2 * B_ASZ;

    const int m0 = blockIdx.x * 128;
    const int n0 = blockIdx.y * 128;
    const int s  = blockIdx.z;
    const int chunk = (C + SPLITK - 1) / SPLITK;
    const int kbeg  = s * chunk;
    const int kend  = min(C, kbeg + chunk);
    const int klen  = kend - kbeg;

    const int tid = threadIdx.x;
    const int tb  = tid >> 4;             // 0..15 m group
    const int to  = tid & 15;             // 0..15 n group
    const int fk  = tid & 15;
    const int fr0 = tid >> 4;

    const unsigned as_u = sptr(As);

    u64 acc[4][8];
    #pragma unroll
    for (int i = 0; i < 4; i++)
        #pragma unroll
        for (int j = 0; j < 8; j++) acc[i][j] = 0ull;

    if (klen > 0) {
        const int nt = (klen + 15) >> 4;
        float wr[8];

        auto fillA = [&](int t, int st) {
            int kg = kbeg + t * 16 + fk;
            if (kg < kend) {
                unsigned dst = as_u + (unsigned)(st * B_ASZ + fk * B_ASTR) * 4u;
                const float* src = A + kg;
                #pragma unroll
                for (int it = 0; it < 8; it++) {
                    int m = fr0 + it * 16;
                    cpa4(dst + (unsigned)m * 4u, src + (size_t)(m0 + m) * C);
                }
            } else {
                float* d = As + st * B_ASZ + fk * B_ASTR;
                #pragma unroll
                for (int it = 0; it < 8; it++) d[fr0 + it * 16] = 0.f;
            }
        };
        auto ldgW = [&](int t) {
            int kg = kbeg + t * 16 + fk;
            #pragma unroll
            for (int it = 0; it < 8; it++) {
                int n = n0 + fr0 + it * 16;
                wr[it] = (n < N_REG && kg < kend) ? Wr[(size_t)n * C + kg] : 0.f;
            }
        };
        auto stsW = [&](int st) {
            float* d = Bs + st * B_WSZ + fk * B_WSTR;
            #pragma unroll
            for (int it = 0; it < 8; it++) {
                int l = fr0 + it * 16;
                *(float2*)(d + (l >> 3) * 20 + (l & 7) * 2) = make_float2(wr[it], wr[it]);
            }
        };
        auto compute = [&](int st) {
            const float* xb = As + st * B_ASZ + tb * 8;
            const float* wb = Bs + st * B_WSZ + to * 20;
            #pragma unroll
            for (int kk = 0; kk < 16; kk++) {
                const ulonglong2* xp = (const ulonglong2*)(xb + kk * B_ASTR);
                const ulonglong2* wp = (const ulonglong2*)(wb + kk * B_WSTR);
                ulonglong2 x01 = xp[0], x23 = xp[1];
                ulonglong2 w01 = wp[0], w23 = wp[1], w45 = wp[2], w67 = wp[3];
                u64 xv[4] = {x01.x, x01.y, x23.x, x23.y};
                u64 wv[8] = {w01.x, w01.y, w23.x, w23.y, w45.x, w45.y, w67.x, w67.y};
                #pragma unroll
                for (int i = 0; i < 4; i++)
                    #pragma unroll
                    for (int j = 0; j < 8; j++)
                        acc[i][j] = fma2(xv[i], wv[j], acc[i][j]);
            }
        };

        fillA(0, 0); cp_commit();
        ldgW(0);
        if (nt > 1) fillA(1, 1);
        cp_commit();
        stsW(0);
        if (nt > 1) ldgW(1);
        cp_wait1();
        __syncthreads();

        for (int t = 0; t < nt; t++) {
            int st = t & 1;
            compute(st);
            __syncthreads();
            if (t + 2 < nt) fillA(t + 2, st);
            cp_commit();
            if (t + 1 < nt) stsW(st ^ 1);
            if (t + 2 < nt) ldgW(t + 2);
            cp_wait1();
            __syncthreads();
        }
    }

    #pragma unroll
    for (int j = 0; j < 8; j++) {
        int n = n0 + to * 8 + j;
        if (n < N_REG) {
            #pragma unroll
            for (int i = 0; i < 4; i++) {
                float2 v = unpack2(acc[i][j]);
                int m = m0 + tb * 8 + 2 * i;
                g_partial[((size_t)s * BATCH + m)     * N_REG + n] = v.x;
                g_partial[((size_t)s * BATCH + m + 1) * N_REG + n] = v.y;
            }
        }
    }
}

// ============================================================
// Stage C: split-K reduce + bias -> reg_out, then cls GEMV + softmax
// ============================================================
__global__ __launch_bounds__(256)
void cls_softmax_kernel(const float* __restrict__ b_reg,
                        const float* __restrict__ W_cls,
                        const float* __restrict__ b_cls,
                        float* __restrict__ reg_out,
                        float* __restrict__ y_pred) {
    const int m = blockIdx.x;
    const int t = threadIdx.x;
    __shared__ float row[N_REG];
    __shared__ float redbuf[256];

    for (int n = t; n < N_REG; n += 256) {
        float sv = b_reg[n];
        #pragma unroll
        for (int k = 0; k < SPLITK; k++)
            sv += g_partial[((size_t)k * BATCH + m) * N_REG + n];
        row[n] = sv;
        reg_out[(size_t)m * N_REG + n] = sv;
    }
    __syncthreads();

    float logit = -1e30f;
    if (t < N_CLS) {
        float sv = b_cls[t];
        const float* w = W_cls + (size_t)t * N_REG;
        #pragma unroll 4
        for (int k = 0; k < N_REG; k++) sv = fmaf(w[k], row[k], sv);
        logit = sv;
    }
    redbuf[t] = logit;
    __syncthreads();
    #pragma unroll
    for (int off = 128; off > 0; off >>= 1) {
        if (t < off) redbuf[t] = fmaxf(redbuf[t], redbuf[t + off]);
        __syncthreads();
    }
    float mx = redbuf[0];
    __syncthreads();
    float e = (t < N_CLS) ? expf(logit - mx) : 0.f;
    redbuf[t] = e;
    __syncthreads();
    #pragma unroll
    for (int off = 128; off > 0; off >>= 1) {
        if (t < off) redbuf[t] += redbuf[t + off];
        __syncthreads();
    }
    float denom = redbuf[0];
    if (t < N_CLS) y_pred[(size_t)m * N_CLS + t] = e / denom;
}

// ============================================================
// Launch
// ============================================================
extern "C" void kernel_launch(void* const* d_in, const int* in_sizes, int n_in,
                              void* d_out, int out_size) {
    const float* x     = (const float*)d_in[0];
    const float* W_enc = (const float*)d_in[1];
    const float* b_enc = (const float*)d_in[2];
    const float* gamma = (const float*)d_in[3];
    const float* beta  = (const float*)d_in[4];
    const float* rmean = (const float*)d_in[5];
    const float* rvar  = (const float*)d_in[6];
    const float* W_reg = (const float*)d_in[7];
    const float* b_reg = (const float*)d_in[8];
    const float* W_cls = (const float*)d_in[9];
    const float* b_cls = (const float*)d_in[10];
    const int*   idx   = (const int*)d_in[11];
    const int*   srci  = (const int*)d_in[12];

    const int total   = in_sizes[0] / BATCH;
    const int max_out = in_sizes[2] / NUM_ROIS;
    const int max_in  = in_sizes[11] / NUM_ROIS;
    const int C       = in_sizes[12];

    float* out        = (float*)d_out;
    float* concat_out = out;
    float* reg_out    = out + (size_t)BATCH * C;
    float* y_pred     = reg_out + (size_t)BATCH * N_REG;

    cudaFuncSetAttribute(roi_enc_kernel,
                         cudaFuncAttributeMaxDynamicSharedMemorySize, A_SMEM);
    cudaFuncSetAttribute(reg_gemm_kernel,
                         cudaFuncAttributeMaxDynamicSharedMemorySize, B_SMEM);

    setup_kernel<<<1, 512>>>(idx, srci, max_in, max_out, total, C);

    dim3 gA(NUM_ROIS, BATCH / 256);
    roi_enc_kernel<<<gA, 256, A_SMEM>>>(x, W_enc, b_enc, gamma, beta, rmean, rvar,
                                        concat_out, total, max_in, max_out, C);

    dim3 gB(BATCH / 128, (N_REG + 127) / 128, SPLITK);
    reg_gemm_kernel<<<gB, 256, B_SMEM>>>(concat_out, W_reg, C);

    cls_softmax_kernel<<<BATCH, 256>>>(b_reg, W_cls, b_cls, reg_out, y_pred);
}